// round 13
// baseline (speedup 1.0000x reference)
#include <cuda_runtime.h>
#include <cstdint>

#define HDIM 1024
#define NEXP 64
#define KTOP 8
#define BM   64
#define KC   64              // k per chunk
#define NCHUNK 16
#define NTHREADS 256

#define ROWB 272             // 68 floats: 16B-aligned, conflict-free LDS.128 (17 odd)
#define TILE (64 * ROWB)     // 17408 B (X tile; W tile same)
#define STG  (2 * TILE)      // 34816 B per stage
#define SMEM_TOTAL (3 * STG) // 104448 B/CTA -> 2 CTAs/SM (208.9KB of 228KB)

__device__ float    g_esum[NEXP];
__device__ int      g_ecnt[NEXP];
__device__ unsigned g_done = 0;

__device__ __forceinline__ unsigned smem_u32(const void* p) {
    return (unsigned)__cvta_generic_to_shared(p);
}
__device__ __forceinline__ void cp16(unsigned dst, const void* src) {
    asm volatile("cp.async.cg.shared.global [%0], [%1], 16;\n" :: "r"(dst), "l"(src));
}
__device__ __forceinline__ void cp_commit() { asm volatile("cp.async.commit_group;\n"); }
__device__ __forceinline__ void cp_wait1()  { asm volatile("cp.async.wait_group 1;\n" ::: "memory"); }

// packed f32x2 FMA: d = a*b + d (componentwise) — rt=2/SMSP (validated by R4 fma%)
__device__ __forceinline__ void fma2(unsigned long long& d,
                                     unsigned long long a,
                                     unsigned long long b) {
    asm("fma.rn.f32x2 %0, %1, %2, %3;" : "=l"(d) : "l"(a), "l"(b), "l"(d));
}
__device__ __forceinline__ float2 unpack2(unsigned long long v) {
    float2 f;
    asm("mov.b64 {%0, %1}, %2;" : "=f"(f.x), "=f"(f.y) : "l"(v));
    return f;
}
__device__ __forceinline__ void lds128u2(ulonglong2& r, unsigned a) {
    asm volatile("ld.shared.v4.u32 {%0,%1,%2,%3}, [%4];"
                 : "=r"(((uint32_t*)&r)[0]), "=r"(((uint32_t*)&r)[1]),
                   "=r"(((uint32_t*)&r)[2]), "=r"(((uint32_t*)&r)[3]) : "r"(a));
}

extern __shared__ char dynsm[];

__global__ __launch_bounds__(NTHREADS, 2)
void gate_k(const float* __restrict__ X, const float* __restrict__ W,
            float* __restrict__ outIdx, float* __restrict__ outW,
            float* __restrict__ outAux, int N) {
    const int tid  = threadIdx.x;
    const int lane = tid & 31;
    const int w    = tid >> 5;
    const int tg   = lane & 7;          // token group within warp
    const int eg   = lane >> 3;         // expert group within warp (0..3)
    const unsigned sbu = smem_u32(dynsm);

    // warp tiling: tokens 32*(w&1) + tg + 8i (i<4); experts 16*(w>>1) + eg + 4j (j<4)
    const int tokBase = 32 * (w & 1) + tg;
    const int expBase = 16 * (w >> 1) + eg;

    const float* Xblk = X + (size_t)blockIdx.x * BM * HDIM;

    // cp.async fill: 1024 X-chunks + 1024 W-chunks per stage; 8 per thread
    const int fr  = tid >> 2;           // row 0..63
    const int fc  = tid & 3;            // 16B chunk base within row
    auto load_tile = [&](int c) {
        unsigned st = sbu + (c % 3) * STG;
        const float* xs = Xblk + (size_t)fr * HDIM + c * KC;
        const float* ws = W   + (size_t)fr * HDIM + c * KC;
        #pragma unroll
        for (int t = 0; t < 4; ++t) {
            int c16 = fc + t * 4;
            cp16(st + (unsigned)(fr * ROWB + c16 * 16), xs + c16 * 4);
            cp16(st + (unsigned)(TILE + fr * ROWB + c16 * 16), ws + c16 * 4);
        }
        cp_commit();
    };

    load_tile(0);
    load_tile(1);

    unsigned long long acc[4][4] = {};   // packed per-chunk chains (32 FMA/component)
    float kS[4][4] = {}, kC[4][4] = {};  // Kahan master + compensation

    const unsigned xoff0 = (unsigned)(tokBase * ROWB);
    const unsigned woff0 = (unsigned)(TILE + expBase * ROWB);

    for (int c = 0; c < NCHUNK; ++c) {
        // race-safe (R12-proven): own-wait -> barrier -> refill
        cp_wait1();
        __syncthreads();
        if (c + 2 < NCHUNK) load_tile(c + 2); else cp_commit();

        const unsigned st = sbu + (c % 3) * STG;
        const unsigned xb = st + xoff0;
        const unsigned wb = st + woff0;

        #pragma unroll 4
        for (int it = 0; it < 16; ++it) {       // 4 k per iteration
            ulonglong2 xv[4], wv[4];
            #pragma unroll
            for (int i = 0; i < 4; ++i)
                lds128u2(xv[i], xb + (unsigned)(i * 8 * ROWB + it * 16));
            #pragma unroll
            for (int j = 0; j < 4; ++j)
                lds128u2(wv[j], wb + (unsigned)(j * 4 * ROWB + it * 16));
            #pragma unroll
            for (int i = 0; i < 4; ++i)
                #pragma unroll
                for (int j = 0; j < 4; ++j) {
                    fma2(acc[i][j], xv[i].x, wv[j].x);
                    fma2(acc[i][j], xv[i].y, wv[j].y);
                }
        }

        // Kahan-fold packed chains (32 FMA/component) into master sums
        #pragma unroll
        for (int i = 0; i < 4; ++i)
            #pragma unroll
            for (int j = 0; j < 4; ++j) {
                float2 f = unpack2(acc[i][j]);
                float t = f.x + f.y;
                float y = t - kC[i][j];
                float s = kS[i][j] + y;
                kC[i][j] = (s - kS[i][j]) - y;
                kS[i][j] = s;
                acc[i][j] = 0ULL;
            }
    }
    __syncthreads();   // all smem reads done -> overlay logits

    // ---- write logits [64][66] ----
    float* lg = (float*)dynsm;
    #pragma unroll
    for (int i = 0; i < 4; ++i)
        #pragma unroll
        for (int j = 0; j < 4; ++j)
            lg[(tokBase + 8 * i) * 66 + expBase + 4 * j] = kS[i][j];
    __syncthreads();

    // ---- softmax + top-8: warp w -> tokens [8w, 8w+8) (R12-proven epilogue) ----
    float ls0 = 0.0f, ls1 = 0.0f;
    int   c0  = 0,    c1  = 0;
    for (int t = w * 8; t < w * 8 + 8; ++t) {
        float l0 = lg[t * 66 + lane];
        float l1 = lg[t * 66 + 32 + lane];
        float m = fmaxf(l0, l1);
        #pragma unroll
        for (int off = 16; off; off >>= 1)
            m = fmaxf(m, __shfl_xor_sync(0xffffffffu, m, off));
        float s0 = expf(l0 - m), s1 = expf(l1 - m);
        float z = s0 + s1;
        #pragma unroll
        for (int off = 16; off; off >>= 1)
            z += __shfl_xor_sync(0xffffffffu, z, off);
        s0 /= z; s1 /= z;
        ls0 += s0; ls1 += s1;

        float r0 = s0, r1 = s1;
        float sumTop = 0.0f, myS = 0.0f;
        int myIdx = 0;
        #pragma unroll
        for (int r = 0; r < KTOP; ++r) {
            float v; int id;
            if (r0 >= r1) { v = r0; id = lane; }       // tie -> lower index
            else          { v = r1; id = lane + 32; }
            #pragma unroll
            for (int off = 16; off; off >>= 1) {
                float v2 = __shfl_xor_sync(0xffffffffu, v, off);
                int   i2 = __shfl_xor_sync(0xffffffffu, id, off);
                if (v2 > v || (v2 == v && i2 < id)) { v = v2; id = i2; }
            }
            sumTop += v;
            if (lane == r) { myS = v; myIdx = id; }
            if (id == lane)           { r0 = -1.0f; c0++; }
            else if (id == lane + 32) { r1 = -1.0f; c1++; }
        }
        if (lane < KTOP) {
            size_t gt = (size_t)(blockIdx.x * BM + t) * KTOP + lane;
            outIdx[gt] = (float)myIdx;
            outW[gt]   = myS / (sumTop + 1e-20f);
        }
    }

    // ---- CTA reduction + 64 global atomics ----
    float* redS = (float*)dynsm + 4224;          // beyond lg (64*66)
    float* redC = redS + 512;
    redS[w * 64 + lane]      = ls0;
    redS[w * 64 + lane + 32] = ls1;
    redC[w * 64 + lane]      = (float)c0;
    redC[w * 64 + lane + 32] = (float)c1;
    __syncthreads();
    if (tid < NEXP) {
        float es = 0.0f, ec = 0.0f;
        #pragma unroll
        for (int ww = 0; ww < 8; ++ww) {
            es += redS[ww * 64 + tid];
            ec += redC[ww * 64 + tid];
        }
        atomicAdd(&g_esum[tid], es);
        if (ec != 0.0f) atomicAdd(&g_ecnt[tid], (int)ec);
    }

    // ---- last-CTA aux finalize ----
    __shared__ unsigned s_isLast;
    __threadfence();
    __syncthreads();
    if (tid == 0)
        s_isLast = (atomicAdd(&g_done, 1u) == gridDim.x - 1) ? 1u : 0u;
    __syncthreads();
    if (s_isLast && tid < 32) {
        float p = g_esum[tid] * (float)g_ecnt[tid]
                + g_esum[tid + 32] * (float)g_ecnt[tid + 32];
        g_esum[tid] = 0.0f;  g_esum[tid + 32] = 0.0f;
        g_ecnt[tid] = 0;     g_ecnt[tid + 32] = 0;
        #pragma unroll
        for (int off = 16; off; off >>= 1)
            p += __shfl_xor_sync(0xffffffffu, p, off);
        if (tid == 0) {
            g_done = 0;
            float denom = (float)N * (float)(N * KTOP);
            *outAux = 0.01f * 64.0f * p / denom;   // ALPHA * E * sum / (N * N*K)
        }
    }
}

extern "C" void kernel_launch(void* const* d_in, const int* in_sizes, int n_in,
                              void* d_out, int out_size) {
    const float* X = (const float*)d_in[0];   // [4,8192,1024] f32
    const float* W = (const float*)d_in[1];   // [64,1024] f32
    float* out = (float*)d_out;               // [idx N*8 | weight N*8 | aux 1]
    int N = in_sizes[0] / HDIM;               // 32768

    cudaFuncSetAttribute(gate_k, cudaFuncAttributeMaxDynamicSharedMemorySize, SMEM_TOTAL);
    gate_k<<<N / BM, NTHREADS, SMEM_TOTAL>>>(X, W, out, out + (size_t)N * KTOP,
                                             out + (size_t)2 * N * KTOP, N);
}

// round 14
// speedup vs baseline: 1.5392x; 1.5392x over previous
#include <cuda_runtime.h>
#include <cuda_fp16.h>
#include <cstdint>

#define HDIM 1024
#define NEXP 64
#define KTOP 8
#define BM   64
#define KC   64
#define NCHUNK 16
#define NTHREADS 256

#define B_STAGE 16384                    // 2 splits x 4 kt x 2 nh x 2 ntp x 32 x 16B
#define SMEM_TOTAL (3 * B_STAGE)         // 49152 B/CTA -> 2 CTAs/SM easily

#define MSCALE   2048.0f                 // 2^11 pre-scale for mid splits
#define MSCALE_I 4.8828125e-4f           // 2^-11

__device__ unsigned short g_wp[2 * 64 * 2 * 2 * 32 * 8];  // W fp16 splits, frag-permuted
__device__ float    g_esum[NEXP];
__device__ int      g_ecnt[NEXP];
__device__ unsigned g_done = 0;

__device__ __forceinline__ unsigned smem_u32(const void* p) {
    return (unsigned)__cvta_generic_to_shared(p);
}
__device__ __forceinline__ void cp16(unsigned dst, const void* src) {
    asm volatile("cp.async.cg.shared.global [%0], [%1], 16;\n" :: "r"(dst), "l"(src));
}
__device__ __forceinline__ void cp_commit() { asm volatile("cp.async.commit_group;\n"); }
__device__ __forceinline__ void cp_wait1()  { asm volatile("cp.async.wait_group 1;\n" ::: "memory"); }

__device__ __forceinline__ void lds128(uint32_t* r, unsigned a) {
    asm volatile("ld.shared.v4.u32 {%0,%1,%2,%3}, [%4];"
                 : "=r"(r[0]), "=r"(r[1]), "=r"(r[2]), "=r"(r[3]) : "r"(a));
}
// D(16x8,f32) += A(16x16,f16 row) x B(16x8,f16 col)
__device__ __forceinline__ void mma16816(float* d, const uint32_t* a, const uint32_t* b) {
    asm volatile("mma.sync.aligned.m16n8k16.row.col.f32.f16.f16.f32 "
                 "{%0,%1,%2,%3}, {%4,%5,%6,%7}, {%8,%9}, {%0,%1,%2,%3};"
                 : "+f"(d[0]), "+f"(d[1]), "+f"(d[2]), "+f"(d[3])
                 : "r"(a[0]), "r"(a[1]), "r"(a[2]), "r"(a[3]), "r"(b[0]), "r"(b[1]));
}
__device__ __forceinline__ uint32_t h2bits(__half2 h) {
    return *reinterpret_cast<uint32_t*>(&h);
}

// Split W into fp16 hi + (mid * 2^11), stored in B-fragment-permuted layout.
__global__ void wsplit_k(const float* __restrict__ W) {
    int i = blockIdx.x * 256 + threadIdx.x;   // i = n*1024 + k
    int n = i >> 10, k = i & 1023;
    float x = W[i];
    __half hh = __float2half_rn(x);
    float r1 = x - __half2float(hh);
    __half hm = __float2half_rn(r1 * MSCALE);
    unsigned short hv[2];
    hv[0] = *reinterpret_cast<unsigned short*>(&hh);
    hv[1] = *reinterpret_cast<unsigned short*>(&hm);

    int kt = k >> 4, kl = k & 15;
    int lane = ((n & 7) << 2) | ((kl >> 1) & 3);
    int reg  = (kl >> 3) & 1;
    int nh   = n >> 5, ntp = (n >> 4) & 1;
    int w4   = ((n >> 3) & 1) * 2 + reg;
    #pragma unroll
    for (int s = 0; s < 2; ++s) {
        size_t off = ((((size_t)s * 64 + kt) * 2 + nh) * 2 + ntp) * 32 + lane;  // 16B units
        g_wp[off * 8 + w4 * 2 + (kl & 1)] = hv[s];
    }
}

extern __shared__ char dynsm[];

__global__ __launch_bounds__(NTHREADS, 2)
void gate_k(const float* __restrict__ X,
            float* __restrict__ outIdx, float* __restrict__ outW,
            float* __restrict__ outAux, int N) {
    const int tid  = threadIdx.x;
    const int lane = tid & 31;
    const int w    = tid >> 5;
    const int mt   = w >> 1;            // m-tile: 16 tokens
    const int nh   = w & 1;             // n-half: 32 experts
    const unsigned sbu = smem_u32(dynsm);

    const float* Xw = X + (size_t)blockIdx.x * BM * HDIM
                        + (size_t)(mt * 16 + (lane >> 2)) * HDIM + (lane & 3) * 2;

    auto loadB = [&](int c) {
        #pragma unroll
        for (int t = 0; t < 4; ++t) {
            int j = tid + t * 256;                  // 1024 16B units per stage
            int s = j >> 9, rem = j & 511;
            cp16(sbu + (c % 3) * B_STAGE + (unsigned)j * 16,
                 (const char*)g_wp + (((size_t)s * 64 + c * 4) * 128 + rem) * 16);
        }
        cp_commit();
    };

    loadB(0);
    loadB(1);

    float accH[4][4] = {}, accM[4][4] = {}, kS[4][4] = {};

    for (int c = 0; c < NCHUNK; ++c) {
        // R12-proven race-safe protocol: own-wait -> barrier -> refill
        cp_wait1();
        __syncthreads();
        if (c + 2 < NCHUNK) loadB(c + 2); else cp_commit();

        // X for this chunk: 8 x LDG.64 batched
        float2 xc[16];
        {
            const float* p = Xw + c * KC;
            #pragma unroll
            for (int kt = 0; kt < 4; ++kt) {
                xc[kt * 4 + 0] = *(const float2*)(p + kt * 16);
                xc[kt * 4 + 1] = *(const float2*)(p + kt * 16 + 8);
                xc[kt * 4 + 2] = *(const float2*)(p + kt * 16 + 8 * HDIM);
                xc[kt * 4 + 3] = *(const float2*)(p + kt * 16 + 8 * HDIM + 8);
            }
        }

        const unsigned bB = sbu + (c % 3) * B_STAGE;
        #pragma unroll
        for (int kt = 0; kt < 4; ++kt) {
            // A fragment -> fp16 hi + (mid * 2^11), in registers
            uint32_t ah[4], am[4];
            {
                const int src[4] = { 4 * kt + 0, 4 * kt + 2, 4 * kt + 1, 4 * kt + 3 };
                #pragma unroll
                for (int f = 0; f < 4; ++f) {
                    float2 v = xc[src[f]];
                    __half2 h2 = __floats2half2_rn(v.x, v.y);
                    float r1x = (v.x - __low2float(h2))  * MSCALE;
                    float r1y = (v.y - __high2float(h2)) * MSCALE;
                    __half2 m2 = __floats2half2_rn(r1x, r1y);
                    ah[f] = h2bits(h2);
                    am[f] = h2bits(m2);
                }
            }
            // B hi split: hh -> accH ; mh -> accM
            #pragma unroll
            for (int ntp = 0; ntp < 2; ++ntp) {
                uint32_t bf[4];
                lds128(bf, bB + (unsigned)(((((0 * 4 + kt) * 2 + nh) * 2 + ntp) * 32 + lane) * 16));
                mma16816(accH[ntp * 2],     ah, bf);
                mma16816(accH[ntp * 2 + 1], ah, bf + 2);
                mma16816(accM[ntp * 2],     am, bf);
                mma16816(accM[ntp * 2 + 1], am, bf + 2);
            }
            // B mid split: hm -> accM
            #pragma unroll
            for (int ntp = 0; ntp < 2; ++ntp) {
                uint32_t bf[4];
                lds128(bf, bB + (unsigned)(((((1 * 4 + kt) * 2 + nh) * 2 + ntp) * 32 + lane) * 16));
                mma16816(accM[ntp * 2],     ah, bf);
                mma16816(accM[ntp * 2 + 1], ah, bf + 2);
            }
        }

        if (c & 1) {  // fold accH (8 accumulate steps) into master — proven schedule
            #pragma unroll
            for (int nt = 0; nt < 4; ++nt)
                #pragma unroll
                for (int q = 0; q < 4; ++q) { kS[nt][q] += accH[nt][q]; accH[nt][q] = 0.0f; }
        }
    }
    __syncthreads();   // all B reads done -> overlay logits on smem

    // ---- write logits [64][66]: logit = kS + accM * 2^-11 ----
    float* lg = (float*)dynsm;
    {
        int r0 = mt * 16 + (lane >> 2);
        int n0 = nh * 32 + (lane & 3) * 2;
        #pragma unroll
        for (int nt = 0; nt < 4; ++nt) {
            float f0 = fmaf(accM[nt][0], MSCALE_I, kS[nt][0]);
            float f1 = fmaf(accM[nt][1], MSCALE_I, kS[nt][1]);
            float f2 = fmaf(accM[nt][2], MSCALE_I, kS[nt][2]);
            float f3 = fmaf(accM[nt][3], MSCALE_I, kS[nt][3]);
            *(float2*)(lg + r0 * 66 + n0 + nt * 8)       = make_float2(f0, f1);
            *(float2*)(lg + (r0 + 8) * 66 + n0 + nt * 8) = make_float2(f2, f3);
        }
    }
    __syncthreads();

    // ---- softmax + top-8: warp w -> tokens [8w, 8w+8) (proven epilogue) ----
    float ls0 = 0.0f, ls1 = 0.0f;
    int   c0  = 0,    c1  = 0;
    for (int t = w * 8; t < w * 8 + 8; ++t) {
        float l0 = lg[t * 66 + lane];
        float l1 = lg[t * 66 + 32 + lane];
        float m = fmaxf(l0, l1);
        #pragma unroll
        for (int off = 16; off; off >>= 1)
            m = fmaxf(m, __shfl_xor_sync(0xffffffffu, m, off));
        float s0 = expf(l0 - m), s1 = expf(l1 - m);
        float z = s0 + s1;
        #pragma unroll
        for (int off = 16; off; off >>= 1)
            z += __shfl_xor_sync(0xffffffffu, z, off);
        s0 /= z; s1 /= z;
        ls0 += s0; ls1 += s1;

        float r0 = s0, r1 = s1;
        float sumTop = 0.0f, myS = 0.0f;
        int myIdx = 0;
        #pragma unroll
        for (int r = 0; r < KTOP; ++r) {
            float v; int id;
            if (r0 >= r1) { v = r0; id = lane; }       // tie -> lower index
            else          { v = r1; id = lane + 32; }
            #pragma unroll
            for (int off = 16; off; off >>= 1) {
                float v2 = __shfl_xor_sync(0xffffffffu, v, off);
                int   i2 = __shfl_xor_sync(0xffffffffu, id, off);
                if (v2 > v || (v2 == v && i2 < id)) { v = v2; id = i2; }
            }
            sumTop += v;
            if (lane == r) { myS = v; myIdx = id; }
            if (id == lane)           { r0 = -1.0f; c0++; }
            else if (id == lane + 32) { r1 = -1.0f; c1++; }
        }
        if (lane < KTOP) {
            size_t gt = (size_t)(blockIdx.x * BM + t) * KTOP + lane;
            outIdx[gt] = (float)myIdx;
            outW[gt]   = myS / (sumTop + 1e-20f);
        }
    }

    // ---- CTA reduction + 64 global atomics ----
    float* redS = (float*)dynsm + 4224;          // beyond lg (64*66)
    float* redC = redS + 512;
    redS[w * 64 + lane]      = ls0;
    redS[w * 64 + lane + 32] = ls1;
    redC[w * 64 + lane]      = (float)c0;
    redC[w * 64 + lane + 32] = (float)c1;
    __syncthreads();
    if (tid < NEXP) {
        float es = 0.0f, ec = 0.0f;
        #pragma unroll
        for (int ww = 0; ww < 8; ++ww) {
            es += redS[ww * 64 + tid];
            ec += redC[ww * 64 + tid];
        }
        atomicAdd(&g_esum[tid], es);
        if (ec != 0.0f) atomicAdd(&g_ecnt[tid], (int)ec);
    }

    // ---- last-CTA aux finalize ----
    __shared__ unsigned s_isLast;
    __threadfence();
    __syncthreads();
    if (tid == 0)
        s_isLast = (atomicAdd(&g_done, 1u) == gridDim.x - 1) ? 1u : 0u;
    __syncthreads();
    if (s_isLast && tid < 32) {
        float p = g_esum[tid] * (float)g_ecnt[tid]
                + g_esum[tid + 32] * (float)g_ecnt[tid + 32];
        g_esum[tid] = 0.0f;  g_esum[tid + 32] = 0.0f;
        g_ecnt[tid] = 0;     g_ecnt[tid + 32] = 0;
        #pragma unroll
        for (int off = 16; off; off >>= 1)
            p += __shfl_xor_sync(0xffffffffu, p, off);
        if (tid == 0) {
            g_done = 0;
            float denom = (float)N * (float)(N * KTOP);
            *outAux = 0.01f * 64.0f * p / denom;   // ALPHA * E * sum / (N * N*K)
        }
    }
}

extern "C" void kernel_launch(void* const* d_in, const int* in_sizes, int n_in,
                              void* d_out, int out_size) {
    const float* X = (const float*)d_in[0];   // [4,8192,1024] f32
    const float* W = (const float*)d_in[1];   // [64,1024] f32
    float* out = (float*)d_out;               // [idx N*8 | weight N*8 | aux 1]
    int N = in_sizes[0] / HDIM;               // 32768

    cudaFuncSetAttribute(gate_k, cudaFuncAttributeMaxDynamicSharedMemorySize, SMEM_TOTAL);
    wsplit_k<<<NEXP * HDIM / 256, 256>>>(W);
    gate_k<<<N / BM, NTHREADS, SMEM_TOTAL>>>(X, out, out + (size_t)N * KTOP,
                                             out + (size_t)2 * N * KTOP, N);
}

// round 15
// speedup vs baseline: 1.7306x; 1.1244x over previous
#include <cuda_runtime.h>
#include <cuda_fp16.h>
#include <cstdint>

#define HDIM 1024
#define NEXP 64
#define KTOP 8
#define BM   64
#define KC   64
#define NCHUNK 16
#define NTHREADS 256

#define XROW 288                         // X smem row stride bytes (72 floats)
#define X_TILE (64 * XROW)               // 18432 B
#define B_TILE 16384                     // 2 splits x 4 kt x 2 nh x 2 ntp x 32 x 16B
#define STG (X_TILE + B_TILE)            // 34816 B
#define SMEM_TOTAL (3 * STG)             // 104448 B/CTA -> 2 CTAs/SM (204KB/228KB)

#define MSCALE   2048.0f                 // 2^11 pre-scale for mid splits
#define MSCALE_I 4.8828125e-4f           // 2^-11

__device__ unsigned short g_wp[2 * 64 * 2 * 2 * 32 * 8];  // W fp16 splits, frag-permuted
__device__ float    g_esum[NEXP];
__device__ int      g_ecnt[NEXP];
__device__ unsigned g_done = 0;

__device__ __forceinline__ unsigned smem_u32(const void* p) {
    return (unsigned)__cvta_generic_to_shared(p);
}
__device__ __forceinline__ void cp16(unsigned dst, const void* src) {
    asm volatile("cp.async.cg.shared.global [%0], [%1], 16;\n" :: "r"(dst), "l"(src));
}
__device__ __forceinline__ void cp_commit() { asm volatile("cp.async.commit_group;\n"); }
__device__ __forceinline__ void cp_wait1()  { asm volatile("cp.async.wait_group 1;\n" ::: "memory"); }

__device__ __forceinline__ void lds128(uint32_t* r, unsigned a) {
    asm volatile("ld.shared.v4.u32 {%0,%1,%2,%3}, [%4];"
                 : "=r"(r[0]), "=r"(r[1]), "=r"(r[2]), "=r"(r[3]) : "r"(a));
}
__device__ __forceinline__ float2 lds64f(unsigned a) {
    float2 v;
    asm volatile("ld.shared.v2.f32 {%0,%1}, [%2];" : "=f"(v.x), "=f"(v.y) : "r"(a));
    return v;
}
// D(16x8,f32) += A(16x16,f16 row) x B(16x8,f16 col)
__device__ __forceinline__ void mma16816(float* d, const uint32_t* a, const uint32_t* b) {
    asm volatile("mma.sync.aligned.m16n8k16.row.col.f32.f16.f16.f32 "
                 "{%0,%1,%2,%3}, {%4,%5,%6,%7}, {%8,%9}, {%0,%1,%2,%3};"
                 : "+f"(d[0]), "+f"(d[1]), "+f"(d[2]), "+f"(d[3])
                 : "r"(a[0]), "r"(a[1]), "r"(a[2]), "r"(a[3]), "r"(b[0]), "r"(b[1]));
}
__device__ __forceinline__ uint32_t h2bits(__half2 h) {
    return *reinterpret_cast<uint32_t*>(&h);
}

// Split W into fp16 hi + (mid * 2^11), stored in B-fragment-permuted layout.
__global__ void wsplit_k(const float* __restrict__ W) {
    int i = blockIdx.x * 256 + threadIdx.x;   // i = n*1024 + k
    int n = i >> 10, k = i & 1023;
    float x = W[i];
    __half hh = __float2half_rn(x);
    float r1 = x - __half2float(hh);
    __half hm = __float2half_rn(r1 * MSCALE);
    unsigned short hv[2];
    hv[0] = *reinterpret_cast<unsigned short*>(&hh);
    hv[1] = *reinterpret_cast<unsigned short*>(&hm);

    int kt = k >> 4, kl = k & 15;
    int lane = ((n & 7) << 2) | ((kl >> 1) & 3);
    int reg  = (kl >> 3) & 1;
    int nh   = n >> 5, ntp = (n >> 4) & 1;
    int w4   = ((n >> 3) & 1) * 2 + reg;
    #pragma unroll
    for (int s = 0; s < 2; ++s) {
        size_t off = ((((size_t)s * 64 + kt) * 2 + nh) * 2 + ntp) * 32 + lane;  // 16B units
        g_wp[off * 8 + w4 * 2 + (kl & 1)] = hv[s];
    }
}

extern __shared__ char dynsm[];

__global__ __launch_bounds__(NTHREADS, 2)
void gate_k(const float* __restrict__ X,
            float* __restrict__ outIdx, float* __restrict__ outW,
            float* __restrict__ outAux, int N) {
    const int tid  = threadIdx.x;
    const int lane = tid & 31;
    const int w    = tid >> 5;
    const int mt   = w >> 1;            // m-tile: 16 tokens
    const int nh   = w & 1;             // n-half: 32 experts
    const unsigned sbu = smem_u32(dynsm);

    const float* Xblk = X + (size_t)blockIdx.x * BM * HDIM;

    // one commit group per chunk: X tile (1024 chunks) + B tile (1024 chunks)
    auto load_tile = [&](int c) {
        unsigned st = sbu + (c % 3) * STG;
        #pragma unroll
        for (int t = 0; t < 4; ++t) {
            int j = tid + t * 256;
            int xr = j >> 4, xc16 = j & 15;
            cp16(st + (unsigned)(xr * XROW + xc16 * 16),
                 Xblk + (size_t)xr * HDIM + c * KC + xc16 * 4);
            int s = j >> 9, rem = j & 511;
            cp16(st + (unsigned)(X_TILE + j * 16),
                 (const char*)g_wp + (((size_t)s * 64 + c * 4) * 128 + rem) * 16);
        }
        cp_commit();
    };

    load_tile(0);
    load_tile(1);

    float accH[4][4] = {}, accM[4][4] = {}, kS[4][4] = {};

    // per-lane X smem offset: row mt*16 + (lane>>2), float2 col (lane&3)
    const unsigned xoff = (unsigned)((mt * 16 + (lane >> 2)) * XROW + (lane & 3) * 8);

    for (int c = 0; c < NCHUNK; ++c) {
        // R12-proven race-safe protocol: own-wait -> barrier -> refill
        cp_wait1();
        __syncthreads();
        if (c + 2 < NCHUNK) load_tile(c + 2); else cp_commit();

        const unsigned st = sbu + (c % 3) * STG;
        const unsigned xb = st + xoff;
        const unsigned bB = st + X_TILE;

        #pragma unroll
        for (int kt = 0; kt < 4; ++kt) {
            // A fragment from smem (4x LDS.64, conflict-free) -> fp16 hi + mid*2^11
            uint32_t ah[4], am[4];
            {
                float2 v[4];
                v[0] = lds64f(xb + kt * 64);               // (r,   k)
                v[1] = lds64f(xb + kt * 64 + 8 * XROW);    // (r+8, k)
                v[2] = lds64f(xb + kt * 64 + 32);          // (r,   k+8)
                v[3] = lds64f(xb + kt * 64 + 8 * XROW + 32); // (r+8, k+8)
                #pragma unroll
                for (int f = 0; f < 4; ++f) {
                    __half2 h2 = __floats2half2_rn(v[f].x, v[f].y);
                    float r1x = (v[f].x - __low2float(h2))  * MSCALE;
                    float r1y = (v[f].y - __high2float(h2)) * MSCALE;
                    __half2 m2 = __floats2half2_rn(r1x, r1y);
                    ah[f] = h2bits(h2);
                    am[f] = h2bits(m2);
                }
            }
            // B hi split: hh -> accH ; mh -> accM
            #pragma unroll
            for (int ntp = 0; ntp < 2; ++ntp) {
                uint32_t bf[4];
                lds128(bf, bB + (unsigned)(((((0 * 4 + kt) * 2 + nh) * 2 + ntp) * 32 + lane) * 16));
                mma16816(accH[ntp * 2],     ah, bf);
                mma16816(accH[ntp * 2 + 1], ah, bf + 2);
                mma16816(accM[ntp * 2],     am, bf);
                mma16816(accM[ntp * 2 + 1], am, bf + 2);
            }
            // B mid split: hm -> accM
            #pragma unroll
            for (int ntp = 0; ntp < 2; ++ntp) {
                uint32_t bf[4];
                lds128(bf, bB + (unsigned)(((((1 * 4 + kt) * 2 + nh) * 2 + ntp) * 32 + lane) * 16));
                mma16816(accM[ntp * 2],     ah, bf);
                mma16816(accM[ntp * 2 + 1], ah, bf + 2);
            }
        }

        if (c & 1) {  // fold accH (8 accumulate steps) into master — proven schedule
            #pragma unroll
            for (int nt = 0; nt < 4; ++nt)
                #pragma unroll
                for (int q = 0; q < 4; ++q) { kS[nt][q] += accH[nt][q]; accH[nt][q] = 0.0f; }
        }
    }
    __syncthreads();   // all smem reads done -> overlay logits

    // ---- write logits [64][66]: logit = kS + accM * 2^-11 ----
    float* lg = (float*)dynsm;
    {
        int r0 = mt * 16 + (lane >> 2);
        int n0 = nh * 32 + (lane & 3) * 2;
        #pragma unroll
        for (int nt = 0; nt < 4; ++nt) {
            float f0 = fmaf(accM[nt][0], MSCALE_I, kS[nt][0]);
            float f1 = fmaf(accM[nt][1], MSCALE_I, kS[nt][1]);
            float f2 = fmaf(accM[nt][2], MSCALE_I, kS[nt][2]);
            float f3 = fmaf(accM[nt][3], MSCALE_I, kS[nt][3]);
            *(float2*)(lg + r0 * 66 + n0 + nt * 8)       = make_float2(f0, f1);
            *(float2*)(lg + (r0 + 8) * 66 + n0 + nt * 8) = make_float2(f2, f3);
        }
    }
    __syncthreads();

    // ---- softmax + top-8: warp w -> tokens [8w, 8w+8) (proven epilogue) ----
    float ls0 = 0.0f, ls1 = 0.0f;
    int   c0  = 0,    c1  = 0;
    for (int t = w * 8; t < w * 8 + 8; ++t) {
        float l0 = lg[t * 66 + lane];
        float l1 = lg[t * 66 + 32 + lane];
        float m = fmaxf(l0, l1);
        #pragma unroll
        for (int off = 16; off; off >>= 1)
            m = fmaxf(m, __shfl_xor_sync(0xffffffffu, m, off));
        float s0 = expf(l0 - m), s1 = expf(l1 - m);
        float z = s0 + s1;
        #pragma unroll
        for (int off = 16; off; off >>= 1)
            z += __shfl_xor_sync(0xffffffffu, z, off);
        s0 /= z; s1 /= z;
        ls0 += s0; ls1 += s1;

        float r0 = s0, r1 = s1;
        float sumTop = 0.0f, myS = 0.0f;
        int myIdx = 0;
        #pragma unroll
        for (int r = 0; r < KTOP; ++r) {
            float v; int id;
            if (r0 >= r1) { v = r0; id = lane; }       // tie -> lower index
            else          { v = r1; id = lane + 32; }
            #pragma unroll
            for (int off = 16; off; off >>= 1) {
                float v2 = __shfl_xor_sync(0xffffffffu, v, off);
                int   i2 = __shfl_xor_sync(0xffffffffu, id, off);
                if (v2 > v || (v2 == v && i2 < id)) { v = v2; id = i2; }
            }
            sumTop += v;
            if (lane == r) { myS = v; myIdx = id; }
            if (id == lane)           { r0 = -1.0f; c0++; }
            else if (id == lane + 32) { r1 = -1.0f; c1++; }
        }
        if (lane < KTOP) {
            size_t gt = (size_t)(blockIdx.x * BM + t) * KTOP + lane;
            outIdx[gt] = (float)myIdx;
            outW[gt]   = myS / (sumTop + 1e-20f);
        }
    }

    // ---- CTA reduction + 64 global atomics ----
    float* redS = (float*)dynsm + 4224;          // beyond lg (64*66)
    float* redC = redS + 512;
    redS[w * 64 + lane]      = ls0;
    redS[w * 64 + lane + 32] = ls1;
    redC[w * 64 + lane]      = (float)c0;
    redC[w * 64 + lane + 32] = (float)c1;
    __syncthreads();
    if (tid < NEXP) {
        float es = 0.0f, ec = 0.0f;
        #pragma unroll
        for (int ww = 0; ww < 8; ++ww) {
            es += redS[ww * 64 + tid];
            ec += redC[ww * 64 + tid];
        }
        atomicAdd(&g_esum[tid], es);
        if (ec != 0.0f) atomicAdd(&g_ecnt[tid], (int)ec);
    }

    // ---- last-CTA aux finalize ----
    __shared__ unsigned s_isLast;
    __threadfence();
    __syncthreads();
    if (tid == 0)
        s_isLast = (atomicAdd(&g_done, 1u) == gridDim.x - 1) ? 1u : 0u;
    __syncthreads();
    if (s_isLast && tid < 32) {
        float p = g_esum[tid] * (float)g_ecnt[tid]
                + g_esum[tid + 32] * (float)g_ecnt[tid + 32];
        g_esum[tid] = 0.0f;  g_esum[tid + 32] = 0.0f;
        g_ecnt[tid] = 0;     g_ecnt[tid + 32] = 0;
        #pragma unroll
        for (int off = 16; off; off >>= 1)
            p += __shfl_xor_sync(0xffffffffu, p, off);
        if (tid == 0) {
            g_done = 0;
            float denom = (float)N * (float)(N * KTOP);
            *outAux = 0.01f * 64.0f * p / denom;   // ALPHA * E * sum / (N * N*K)
        }
    }
}

extern "C" void kernel_launch(void* const* d_in, const int* in_sizes, int n_in,
                              void* d_out, int out_size) {
    const float* X = (const float*)d_in[0];   // [4,8192,1024] f32
    const float* W = (const float*)d_in[1];   // [64,1024] f32
    float* out = (float*)d_out;               // [idx N*8 | weight N*8 | aux 1]
    int N = in_sizes[0] / HDIM;               // 32768

    cudaFuncSetAttribute(gate_k, cudaFuncAttributeMaxDynamicSharedMemorySize, SMEM_TOTAL);
    wsplit_k<<<NEXP * HDIM / 256, 256>>>(W);
    gate_k<<<N / BM, NTHREADS, SMEM_TOTAL>>>(X, out, out + (size_t)N * KTOP,
                                             out + (size_t)2 * N * KTOP, N);
}